// round 1
// baseline (speedup 1.0000x reference)
#include <cuda_runtime.h>
#include <math.h>

#define NN    10000
#define EIN   160000
#define ETOT  170000
#define NHEAD 8
#define HID   256
#define EPSI  1e-5f
#define SLOPE 0.2f

// ---------------- scratch (device globals; no allocation allowed) ----------------
__device__ float d_h0[NN * HID];            // x @ W0           [N,256]
__device__ float d_hin[NN * HID];           // elu(bn(layer0))  [N,256]
__device__ float d_h1[NN * HID * NHEAD];    // hin @ W1         [N,2048]
__device__ float d_out0[NN * HID];
__device__ float d_out1[NN * HID];
__device__ float d_h2[NN * HID];
__device__ float d_ss[NN * NHEAD];
__device__ float d_sd[NN * NHEAD];
__device__ int   d_counts[NN + 1];
__device__ int   d_offsets[NN + 1];
__device__ int   d_cursor[NN];
__device__ int   d_srcs[ETOT];
__device__ float d_alpha[ETOT * NHEAD];
__device__ float d_bnsum[HID];
__device__ float d_bnsum2[HID];
__device__ float d_mu[HID];
__device__ float d_rinv[HID];

// ---------------- CSR build ----------------
__global__ void count_kernel(const int* __restrict__ dst) {
    int i = blockIdx.x * blockDim.x + threadIdx.x;
    if (i >= ETOT) return;
    int d = (i < EIN) ? dst[i] : (i - EIN);
    atomicAdd(&d_counts[d], 1);
}

__global__ void scan_kernel() {
    __shared__ int sums[1024];
    const int n = NN;
    const int chunk = (n + 1023) / 1024;   // 10
    int tid = threadIdx.x;
    int start = tid * chunk;
    int local = 0;
    for (int i = 0; i < chunk; i++)
        if (start + i < n) local += d_counts[start + i];
    sums[tid] = local;
    __syncthreads();
    for (int off = 1; off < 1024; off <<= 1) {
        int v = (tid >= off) ? sums[tid - off] : 0;
        __syncthreads();
        sums[tid] += v;
        __syncthreads();
    }
    int run = (tid == 0) ? 0 : sums[tid - 1];
    for (int i = 0; i < chunk; i++) {
        if (start + i < n) {
            d_offsets[start + i] = run;
            run += d_counts[start + i];
        }
    }
    if (tid == 1023) d_offsets[n] = sums[1023];
}

__global__ void place_kernel(const int* __restrict__ src, const int* __restrict__ dst) {
    int i = blockIdx.x * blockDim.x + threadIdx.x;
    if (i >= ETOT) return;
    int s, d;
    if (i < EIN) { s = src[i]; d = dst[i]; }
    else         { s = d = i - EIN; }
    int pos = d_offsets[d] + atomicAdd(&d_cursor[d], 1);
    d_srcs[pos] = s;
}

// ---------------- attention scores s_src / s_dst ----------------
// warp per (node, head): s[n,h] = dot(h[n,h,:], a[h,:])
__global__ void attn_scores(const float* __restrict__ h,
                            const float* __restrict__ a_src,
                            const float* __restrict__ a_dst, int C) {
    int w = (blockIdx.x * blockDim.x + threadIdx.x) >> 5;
    if (w >= NN * NHEAD) return;
    int node = w / NHEAD, head = w % NHEAD;
    int lane = threadIdx.x & 31;
    const float* hp = h + (size_t)node * NHEAD * C + head * C;
    const float* asrc = a_src + head * C;
    const float* adst = a_dst + head * C;
    float ss = 0.f, sd = 0.f;
    for (int c = lane; c < C; c += 32) {
        float hv = hp[c];
        ss += hv * asrc[c];
        sd += hv * adst[c];
    }
    #pragma unroll
    for (int o = 16; o > 0; o >>= 1) {
        ss += __shfl_xor_sync(0xffffffffu, ss, o);
        sd += __shfl_xor_sync(0xffffffffu, sd, o);
    }
    if (lane == 0) {
        d_ss[node * NHEAD + head] = ss;
        d_sd[node * NHEAD + head] = sd;
    }
}

// ---------------- per-dst edge softmax (writes alpha in CSR order) ----------------
__global__ void edge_softmax() {
    int w = (blockIdx.x * blockDim.x + threadIdx.x) >> 5;
    if (w >= NN) return;
    int lane = threadIdx.x & 31;
    int beg = d_offsets[w], end = d_offsets[w + 1];
    float sd[NHEAD];
    #pragma unroll
    for (int h = 0; h < NHEAD; h++) sd[h] = d_sd[w * NHEAD + h];

    float mx[NHEAD];
    #pragma unroll
    for (int h = 0; h < NHEAD; h++) mx[h] = -1e30f;
    for (int p = beg + lane; p < end; p += 32) {
        int s = d_srcs[p];
        #pragma unroll
        for (int h = 0; h < NHEAD; h++) {
            float sc = d_ss[s * NHEAD + h] + sd[h];
            sc = (sc >= 0.f) ? sc : SLOPE * sc;
            mx[h] = fmaxf(mx[h], sc);
        }
    }
    #pragma unroll
    for (int h = 0; h < NHEAD; h++)
        #pragma unroll
        for (int o = 16; o > 0; o >>= 1)
            mx[h] = fmaxf(mx[h], __shfl_xor_sync(0xffffffffu, mx[h], o));

    float sum[NHEAD];
    #pragma unroll
    for (int h = 0; h < NHEAD; h++) sum[h] = 0.f;
    for (int p = beg + lane; p < end; p += 32) {
        int s = d_srcs[p];
        #pragma unroll
        for (int h = 0; h < NHEAD; h++) {
            float sc = d_ss[s * NHEAD + h] + sd[h];
            sc = (sc >= 0.f) ? sc : SLOPE * sc;
            sum[h] += __expf(sc - mx[h]);
        }
    }
    #pragma unroll
    for (int h = 0; h < NHEAD; h++)
        #pragma unroll
        for (int o = 16; o > 0; o >>= 1)
            sum[h] += __shfl_xor_sync(0xffffffffu, sum[h], o);

    float rinv[NHEAD];
    #pragma unroll
    for (int h = 0; h < NHEAD; h++) rinv[h] = 1.f / sum[h];

    for (int p = beg + lane; p < end; p += 32) {
        int s = d_srcs[p];
        #pragma unroll
        for (int h = 0; h < NHEAD; h++) {
            float sc = d_ss[s * NHEAD + h] + sd[h];
            sc = (sc >= 0.f) ? sc : SLOPE * sc;
            d_alpha[p * NHEAD + h] = __expf(sc - mx[h]) * rinv[h];
        }
    }
}

// ---------------- aggregation ----------------
// layer0: C=32, concat -> 256 channels; thread t handles channel t, head=t>>5
__global__ void aggregate_c32(const float* __restrict__ h,
                              const float* __restrict__ bias,
                              float* __restrict__ out) {
    int nod = blockIdx.x;
    int t = threadIdx.x;
    int head = t >> 5;
    int beg = d_offsets[nod], end = d_offsets[nod + 1];
    float acc = 0.f;
    for (int p = beg; p < end; p++) {
        float a = d_alpha[p * NHEAD + head];
        acc = fmaf(h[(size_t)d_srcs[p] * HID + t], a, acc);
    }
    out[(size_t)nod * HID + t] = acc + bias[t];
}

// layer1: C=256 per head, mean over heads; thread t = channel c, 8 head accumulators
__global__ void aggregate_c256_mean(const float* __restrict__ h,
                                    const float* __restrict__ bias,
                                    float* __restrict__ out) {
    int nod = blockIdx.x;
    int t = threadIdx.x;
    int beg = d_offsets[nod], end = d_offsets[nod + 1];
    float acc[NHEAD];
    #pragma unroll
    for (int i = 0; i < NHEAD; i++) acc[i] = 0.f;
    for (int p = beg; p < end; p++) {
        int s = d_srcs[p];
        float al[NHEAD];
        #pragma unroll
        for (int i = 0; i < NHEAD; i++) al[i] = d_alpha[p * NHEAD + i];
        const float* hp = h + (size_t)s * (HID * NHEAD);
        #pragma unroll
        for (int i = 0; i < NHEAD; i++)
            acc[i] = fmaf(hp[i * HID + t], al[i], acc[i]);
    }
    float s8 = 0.f;
    #pragma unroll
    for (int i = 0; i < NHEAD; i++) s8 += acc[i];
    out[(size_t)nod * HID + t] = s8 * (1.f / NHEAD) + bias[t];
}

// ---------------- batch norm ----------------
__global__ void bn_partial(const float* __restrict__ x) {
    int c = threadIdx.x;                   // 256 channels
    int nb = gridDim.x;
    int rows = (NN + nb - 1) / nb;
    int r0 = blockIdx.x * rows;
    int r1 = min(NN, r0 + rows);
    float s = 0.f, s2 = 0.f;
    for (int r = r0; r < r1; r++) {
        float v = x[(size_t)r * HID + c];
        s += v; s2 += v * v;
    }
    atomicAdd(&d_bnsum[c], s);
    atomicAdd(&d_bnsum2[c], s2);
}

__global__ void bn_final() {
    int c = threadIdx.x;
    float m = d_bnsum[c] * (1.f / NN);
    float v = d_bnsum2[c] * (1.f / NN) - m * m;
    d_mu[c] = m;
    d_rinv[c] = rsqrtf(v + EPSI);
}

__global__ void bn_apply(const float* __restrict__ x,
                         const float* __restrict__ g,
                         const float* __restrict__ be,
                         const float* __restrict__ resid,
                         float* __restrict__ out) {
    int i = blockIdx.x * blockDim.x + threadIdx.x;
    if (i >= NN * HID) return;
    int c = i & (HID - 1);
    float v = g[c] * (x[i] - d_mu[c]) * d_rinv[c] + be[c];
    v = (v > 0.f) ? v : (expf(v) - 1.f);
    if (resid) v += resid[i];
    out[i] = v;
}

// ---------------- tiled fp32 GEMM: C[M,N] = A[M,K] @ B[K,N] (+bias) ----------------
__global__ __launch_bounds__(256) void gemm64(const float* __restrict__ A,
                                              const float* __restrict__ B,
                                              float* __restrict__ C,
                                              const float* __restrict__ bias,
                                              int M, int Nc, int K) {
    __shared__ float As[16][68];   // [k][m], padded for 16B-aligned float4
    __shared__ float Bs[16][68];   // [k][n]
    int tid = threadIdx.x;
    int tx = tid & 15, ty = tid >> 4;
    int row0 = blockIdx.y * 64, col0 = blockIdx.x * 64;
    float acc[4][4];
    #pragma unroll
    for (int i = 0; i < 4; i++)
        #pragma unroll
        for (int j = 0; j < 4; j++) acc[i][j] = 0.f;

    for (int k0 = 0; k0 < K; k0 += 16) {
        #pragma unroll
        for (int i = 0; i < 4; i++) {
            int idx = tid + i * 256;
            int r = idx >> 4, c = idx & 15;        // A tile 64x16
            int gr = row0 + r;
            As[c][r] = (gr < M) ? A[(size_t)gr * K + k0 + c] : 0.f;
            int r2 = idx >> 6, c2 = idx & 63;      // B tile 16x64
            int gc = col0 + c2;
            Bs[r2][c2] = (gc < Nc) ? B[(size_t)(k0 + r2) * Nc + gc] : 0.f;
        }
        __syncthreads();
        #pragma unroll
        for (int k = 0; k < 16; k++) {
            float4 a4 = *(const float4*)&As[k][ty * 4];
            float4 b4 = *(const float4*)&Bs[k][tx * 4];
            float av[4] = {a4.x, a4.y, a4.z, a4.w};
            float bv[4] = {b4.x, b4.y, b4.z, b4.w};
            #pragma unroll
            for (int i = 0; i < 4; i++)
                #pragma unroll
                for (int j = 0; j < 4; j++)
                    acc[i][j] = fmaf(av[i], bv[j], acc[i][j]);
        }
        __syncthreads();
    }
    #pragma unroll
    for (int i = 0; i < 4; i++) {
        int gr = row0 + ty * 4 + i;
        if (gr >= M) continue;
        #pragma unroll
        for (int j = 0; j < 4; j++) {
            int gc = col0 + tx * 4 + j;
            if (gc < Nc)
                C[(size_t)gr * Nc + gc] = acc[i][j] + (bias ? bias[gc] : 0.f);
        }
    }
}

// ---------------- host launcher ----------------
extern "C" void kernel_launch(void* const* d_in, const int* in_sizes, int n_in,
                              void* d_out, int out_size) {
    (void)in_sizes; (void)n_in; (void)out_size;
    const float* x   = (const float*)d_in[0];
    const int*   ei  = (const int*)d_in[1];
    const float* W0  = (const float*)d_in[2];
    const float* as0 = (const float*)d_in[3];
    const float* ad0 = (const float*)d_in[4];
    const float* b0  = (const float*)d_in[5];
    const float* g0  = (const float*)d_in[6];
    const float* be0 = (const float*)d_in[7];
    const float* W1  = (const float*)d_in[8];
    const float* as1 = (const float*)d_in[9];
    const float* ad1 = (const float*)d_in[10];
    const float* b1  = (const float*)d_in[11];
    const float* g1  = (const float*)d_in[12];
    const float* be1 = (const float*)d_in[13];
    const float* Wc  = (const float*)d_in[14];
    const float* bc  = (const float*)d_in[15];
    float* out = (float*)d_out;
    const int* srcp = ei;
    const int* dstp = ei + EIN;

    void *p_counts, *p_cursor, *p_bnsum, *p_bnsum2;
    void *p_h0, *p_hin, *p_h1, *p_h2, *p_out0, *p_out1;
    cudaGetSymbolAddress(&p_counts, d_counts);
    cudaGetSymbolAddress(&p_cursor, d_cursor);
    cudaGetSymbolAddress(&p_bnsum,  d_bnsum);
    cudaGetSymbolAddress(&p_bnsum2, d_bnsum2);
    cudaGetSymbolAddress(&p_h0,   d_h0);
    cudaGetSymbolAddress(&p_hin,  d_hin);
    cudaGetSymbolAddress(&p_h1,   d_h1);
    cudaGetSymbolAddress(&p_h2,   d_h2);
    cudaGetSymbolAddress(&p_out0, d_out0);
    cudaGetSymbolAddress(&p_out1, d_out1);
    float* h0   = (float*)p_h0;
    float* hin  = (float*)p_hin;
    float* h1   = (float*)p_h1;
    float* h2   = (float*)p_h2;
    float* out0 = (float*)p_out0;
    float* out1 = (float*)p_out1;

    // ---- CSR build (shared by both layers) ----
    cudaMemsetAsync(p_counts, 0, (NN + 1) * sizeof(int));
    cudaMemsetAsync(p_cursor, 0, NN * sizeof(int));
    count_kernel<<<(ETOT + 255) / 256, 256>>>(dstp);
    scan_kernel<<<1, 1024>>>();
    place_kernel<<<(ETOT + 255) / 256, 256>>>(srcp, dstp);

    // ---- layer 0 ----
    gemm64<<<dim3(HID / 64, (NN + 63) / 64), 256>>>(x, W0, h0, nullptr, NN, HID, HID);
    attn_scores<<<(NN * NHEAD) / 8, 256>>>(h0, as0, ad0, HID / NHEAD);
    edge_softmax<<<(NN + 3) / 4, 128>>>();
    aggregate_c32<<<NN, HID>>>(h0, b0, out0);
    cudaMemsetAsync(p_bnsum, 0, HID * sizeof(float));
    cudaMemsetAsync(p_bnsum2, 0, HID * sizeof(float));
    bn_partial<<<128, HID>>>(out0);
    bn_final<<<1, HID>>>();
    bn_apply<<<(NN * HID + 255) / 256, 256>>>(out0, g0, be0, nullptr, hin);

    // ---- layer 1 ----
    gemm64<<<dim3((NHEAD * HID) / 64, (NN + 63) / 64), 256>>>(hin, W1, h1, nullptr, NN, NHEAD * HID, HID);
    attn_scores<<<(NN * NHEAD) / 8, 256>>>(h1, as1, ad1, HID);
    edge_softmax<<<(NN + 3) / 4, 128>>>();
    aggregate_c256_mean<<<NN, HID>>>(h1, b1, out1);
    cudaMemsetAsync(p_bnsum, 0, HID * sizeof(float));
    cudaMemsetAsync(p_bnsum2, 0, HID * sizeof(float));
    bn_partial<<<128, HID>>>(out1);
    bn_final<<<1, HID>>>();
    bn_apply<<<(NN * HID + 255) / 256, 256>>>(out1, g1, be1, hin, h2);

    // ---- classifier ----
    gemm64<<<dim3(1, (NN + 63) / 64), 256>>>(h2, Wc, out, bc, NN, 40, HID);
}

// round 2
// speedup vs baseline: 1.1046x; 1.1046x over previous
#include <cuda_runtime.h>
#include <math.h>

#define NN    10000
#define EIN   160000
#define ETOT  170000
#define NHEAD 8
#define HID   256
#define EPSI  1e-5f
#define SLOPE 0.2f

// ---------------- scratch (device globals; no allocation allowed) ----------------
__device__ float d_h0[NN * HID];            // x @ W0           [N,256]
__device__ float d_hin[NN * HID];           // elu(bn(layer0))  [N,256]
__device__ float d_h1[NN * HID * NHEAD];    // hin @ W1         [N,2048]
__device__ float d_out0[NN * HID];
__device__ float d_out1[NN * HID];
__device__ float d_h2[NN * HID];
__device__ float d_ss[NN * NHEAD];
__device__ float d_sd[NN * NHEAD];
__device__ int   d_counts[NN + 1];
__device__ int   d_offsets[NN + 1];
__device__ int   d_cursor[NN];
__device__ int   d_srcs[ETOT];
__device__ float d_alpha[ETOT * NHEAD];
__device__ float d_bnsum[HID];
__device__ float d_bnsum2[HID];
__device__ float d_mu[HID];
__device__ float d_rinv[HID];

// ---------------- CSR build ----------------
__global__ void count_kernel(const int* __restrict__ dst) {
    int i = blockIdx.x * blockDim.x + threadIdx.x;
    if (i >= ETOT) return;
    int d = (i < EIN) ? dst[i] : (i - EIN);
    atomicAdd(&d_counts[d], 1);
}

__global__ void scan_kernel() {
    __shared__ int sums[1024];
    const int n = NN;
    const int chunk = (n + 1023) / 1024;   // 10
    int tid = threadIdx.x;
    int start = tid * chunk;
    int local = 0;
    for (int i = 0; i < chunk; i++)
        if (start + i < n) local += d_counts[start + i];
    sums[tid] = local;
    __syncthreads();
    for (int off = 1; off < 1024; off <<= 1) {
        int v = (tid >= off) ? sums[tid - off] : 0;
        __syncthreads();
        sums[tid] += v;
        __syncthreads();
    }
    int run = (tid == 0) ? 0 : sums[tid - 1];
    for (int i = 0; i < chunk; i++) {
        if (start + i < n) {
            d_offsets[start + i] = run;
            run += d_counts[start + i];
        }
    }
    if (tid == 1023) d_offsets[n] = sums[1023];
}

__global__ void place_kernel(const int* __restrict__ src, const int* __restrict__ dst) {
    int i = blockIdx.x * blockDim.x + threadIdx.x;
    if (i >= ETOT) return;
    int s, d;
    if (i < EIN) { s = src[i]; d = dst[i]; }
    else         { s = d = i - EIN; }
    int pos = d_offsets[d] + atomicAdd(&d_cursor[d], 1);
    d_srcs[pos] = s;
}

// ---------------- attention scores s_src / s_dst ----------------
__global__ void attn_scores(const float* __restrict__ h,
                            const float* __restrict__ a_src,
                            const float* __restrict__ a_dst, int C) {
    int w = (blockIdx.x * blockDim.x + threadIdx.x) >> 5;
    if (w >= NN * NHEAD) return;
    int node = w / NHEAD, head = w % NHEAD;
    int lane = threadIdx.x & 31;
    const float* hp = h + (size_t)node * NHEAD * C + head * C;
    const float* asrc = a_src + head * C;
    const float* adst = a_dst + head * C;
    float ss = 0.f, sd = 0.f;
    for (int c = lane; c < C; c += 32) {
        float hv = hp[c];
        ss += hv * asrc[c];
        sd += hv * adst[c];
    }
    #pragma unroll
    for (int o = 16; o > 0; o >>= 1) {
        ss += __shfl_xor_sync(0xffffffffu, ss, o);
        sd += __shfl_xor_sync(0xffffffffu, sd, o);
    }
    if (lane == 0) {
        d_ss[node * NHEAD + head] = ss;
        d_sd[node * NHEAD + head] = sd;
    }
}

// ---------------- per-dst edge softmax ----------------
__global__ void edge_softmax() {
    int w = (blockIdx.x * blockDim.x + threadIdx.x) >> 5;
    if (w >= NN) return;
    int lane = threadIdx.x & 31;
    int beg = d_offsets[w], end = d_offsets[w + 1];
    float sd[NHEAD];
    #pragma unroll
    for (int h = 0; h < NHEAD; h++) sd[h] = d_sd[w * NHEAD + h];

    float mx[NHEAD];
    #pragma unroll
    for (int h = 0; h < NHEAD; h++) mx[h] = -1e30f;
    for (int p = beg + lane; p < end; p += 32) {
        int s = d_srcs[p];
        #pragma unroll
        for (int h = 0; h < NHEAD; h++) {
            float sc = d_ss[s * NHEAD + h] + sd[h];
            sc = (sc >= 0.f) ? sc : SLOPE * sc;
            mx[h] = fmaxf(mx[h], sc);
        }
    }
    #pragma unroll
    for (int h = 0; h < NHEAD; h++)
        #pragma unroll
        for (int o = 16; o > 0; o >>= 1)
            mx[h] = fmaxf(mx[h], __shfl_xor_sync(0xffffffffu, mx[h], o));

    float sum[NHEAD];
    #pragma unroll
    for (int h = 0; h < NHEAD; h++) sum[h] = 0.f;
    for (int p = beg + lane; p < end; p += 32) {
        int s = d_srcs[p];
        #pragma unroll
        for (int h = 0; h < NHEAD; h++) {
            float sc = d_ss[s * NHEAD + h] + sd[h];
            sc = (sc >= 0.f) ? sc : SLOPE * sc;
            sum[h] += __expf(sc - mx[h]);
        }
    }
    #pragma unroll
    for (int h = 0; h < NHEAD; h++)
        #pragma unroll
        for (int o = 16; o > 0; o >>= 1)
            sum[h] += __shfl_xor_sync(0xffffffffu, sum[h], o);

    float rinv[NHEAD];
    #pragma unroll
    for (int h = 0; h < NHEAD; h++) rinv[h] = 1.f / sum[h];

    for (int p = beg + lane; p < end; p += 32) {
        int s = d_srcs[p];
        #pragma unroll
        for (int h = 0; h < NHEAD; h++) {
            float sc = d_ss[s * NHEAD + h] + sd[h];
            sc = (sc >= 0.f) ? sc : SLOPE * sc;
            d_alpha[p * NHEAD + h] = __expf(sc - mx[h]) * rinv[h];
        }
    }
}

// ---------------- aggregation ----------------
__global__ void aggregate_c32(const float* __restrict__ h,
                              const float* __restrict__ bias,
                              float* __restrict__ out) {
    int nod = blockIdx.x;
    int t = threadIdx.x;
    int head = t >> 5;
    int beg = d_offsets[nod], end = d_offsets[nod + 1];
    float acc = 0.f;
    for (int p = beg; p < end; p++) {
        float a = d_alpha[p * NHEAD + head];
        acc = fmaf(h[(size_t)d_srcs[p] * HID + t], a, acc);
    }
    out[(size_t)nod * HID + t] = acc + bias[t];
}

__global__ void aggregate_c256_mean(const float* __restrict__ h,
                                    const float* __restrict__ bias,
                                    float* __restrict__ out) {
    int nod = blockIdx.x;
    int t = threadIdx.x;
    int beg = d_offsets[nod], end = d_offsets[nod + 1];
    float acc[NHEAD];
    #pragma unroll
    for (int i = 0; i < NHEAD; i++) acc[i] = 0.f;
    for (int p = beg; p < end; p++) {
        int s = d_srcs[p];
        float al[NHEAD];
        #pragma unroll
        for (int i = 0; i < NHEAD; i++) al[i] = d_alpha[p * NHEAD + i];
        const float* hp = h + (size_t)s * (HID * NHEAD);
        #pragma unroll
        for (int i = 0; i < NHEAD; i++)
            acc[i] = fmaf(hp[i * HID + t], al[i], acc[i]);
    }
    float s8 = 0.f;
    #pragma unroll
    for (int i = 0; i < NHEAD; i++) s8 += acc[i];
    out[(size_t)nod * HID + t] = s8 * (1.f / NHEAD) + bias[t];
}

// ---------------- batch norm ----------------
__global__ void bn_partial(const float* __restrict__ x) {
    int c = threadIdx.x;
    int nb = gridDim.x;
    int rows = (NN + nb - 1) / nb;
    int r0 = blockIdx.x * rows;
    int r1 = min(NN, r0 + rows);
    float s = 0.f, s2 = 0.f;
    for (int r = r0; r < r1; r++) {
        float v = x[(size_t)r * HID + c];
        s += v; s2 += v * v;
    }
    atomicAdd(&d_bnsum[c], s);
    atomicAdd(&d_bnsum2[c], s2);
}

__global__ void bn_final() {
    int c = threadIdx.x;
    float m = d_bnsum[c] * (1.f / NN);
    float v = d_bnsum2[c] * (1.f / NN) - m * m;
    d_mu[c] = m;
    d_rinv[c] = rsqrtf(v + EPSI);
}

__global__ void bn_apply(const float* __restrict__ x,
                         const float* __restrict__ g,
                         const float* __restrict__ be,
                         const float* __restrict__ resid,
                         float* __restrict__ out) {
    int i = blockIdx.x * blockDim.x + threadIdx.x;
    if (i >= NN * HID) return;
    int c = i & (HID - 1);
    float v = g[c] * (x[i] - d_mu[c]) * d_rinv[c] + be[c];
    v = (v > 0.f) ? v : (expf(v) - 1.f);
    if (resid) v += resid[i];
    out[i] = v;
}

// ---------------- 128x128x8 double-buffered fp32 GEMM ----------------
// C[M,Nc] = A[M,K] @ B[K,Nc] (+bias). K must be a multiple of 8.
__global__ __launch_bounds__(256, 2) void gemm128(const float* __restrict__ A,
                                                  const float* __restrict__ B,
                                                  float* __restrict__ C,
                                                  const float* __restrict__ bias,
                                                  int M, int Nc, int K) {
    __shared__ float As[2][8][132];   // [buf][k][m]
    __shared__ float Bs[2][8][132];   // [buf][k][n]

    const int tid  = threadIdx.x;
    const int row0 = blockIdx.y * 128;
    const int col0 = blockIdx.x * 128;

    // global-load mapping
    const int arow = tid >> 1;           // 0..127
    const int akg  = (tid & 1) * 4;      // k-subgroup 0 or 4
    const int bkr  = tid >> 5;           // 0..7  (k row of B tile)
    const int bc4  = (tid & 31) * 4;     // 0..124

    // compute mapping: 8 warps as 4(m) x 2(n); thread 4x8 in warp
    const int lane = tid & 31;
    const int warp = tid >> 5;
    const int m0 = (warp & 3) * 32 + (lane >> 3) * 4;   // + {0..3, 16..19}
    const int n0 = (warp >> 2) * 64 + (lane & 7) * 4;   // + {0..3, 32..35}

    const int gra = row0 + arow;
    const int gcb = col0 + bc4;

    float accv[8][8];
    #pragma unroll
    for (int i = 0; i < 8; i++)
        #pragma unroll
        for (int j = 0; j < 8; j++) accv[i][j] = 0.f;

    float aL[4], bL[4];

    // tile loaders (global -> registers)
    auto load_tile = [&](int k0) {
        if (gra < M) {
            const float4 v = *(const float4*)&A[(size_t)gra * K + k0 + akg];
            aL[0] = v.x; aL[1] = v.y; aL[2] = v.z; aL[3] = v.w;
        } else {
            aL[0] = aL[1] = aL[2] = aL[3] = 0.f;
        }
        const float* Brow = B + (size_t)(k0 + bkr) * Nc;
        if (gcb + 4 <= Nc) {
            const float4 v = *(const float4*)&Brow[gcb];
            bL[0] = v.x; bL[1] = v.y; bL[2] = v.z; bL[3] = v.w;
        } else {
            #pragma unroll
            for (int i = 0; i < 4; i++)
                bL[i] = (gcb + i < Nc) ? Brow[gcb + i] : 0.f;
        }
    };
    auto store_tile = [&](int buf) {
        #pragma unroll
        for (int i = 0; i < 4; i++) As[buf][akg + i][arow] = aL[i];
        *(float4*)&Bs[buf][bkr][bc4] = make_float4(bL[0], bL[1], bL[2], bL[3]);
    };

    load_tile(0);
    store_tile(0);
    __syncthreads();

    const int ntiles = K >> 3;
    for (int t = 0; t < ntiles; t++) {
        const int buf = t & 1;
        if (t + 1 < ntiles) load_tile((t + 1) << 3);
        #pragma unroll
        for (int k = 0; k < 8; k++) {
            float a[8], b[8];
            *(float4*)&a[0] = *(const float4*)&As[buf][k][m0];
            *(float4*)&a[4] = *(const float4*)&As[buf][k][m0 + 16];
            *(float4*)&b[0] = *(const float4*)&Bs[buf][k][n0];
            *(float4*)&b[4] = *(const float4*)&Bs[buf][k][n0 + 32];
            #pragma unroll
            for (int i = 0; i < 8; i++)
                #pragma unroll
                for (int j = 0; j < 8; j++)
                    accv[i][j] = fmaf(a[i], b[j], accv[i][j]);
        }
        if (t + 1 < ntiles) {
            store_tile(buf ^ 1);
            __syncthreads();
        }
    }

    // epilogue
    #pragma unroll
    for (int i = 0; i < 8; i++) {
        const int gm = row0 + ((i < 4) ? (m0 + i) : (m0 + 16 + i - 4));
        if (gm >= M) continue;
        float* Crow = C + (size_t)gm * Nc;
        #pragma unroll
        for (int jj = 0; jj < 2; jj++) {
            const int gn = col0 + n0 + jj * 32;
            if (gn + 4 <= Nc) {
                float4 v;
                v.x = accv[i][jj * 4 + 0] + (bias ? bias[gn + 0] : 0.f);
                v.y = accv[i][jj * 4 + 1] + (bias ? bias[gn + 1] : 0.f);
                v.z = accv[i][jj * 4 + 2] + (bias ? bias[gn + 2] : 0.f);
                v.w = accv[i][jj * 4 + 3] + (bias ? bias[gn + 3] : 0.f);
                *(float4*)&Crow[gn] = v;
            } else {
                #pragma unroll
                for (int j = 0; j < 4; j++)
                    if (gn + j < Nc)
                        Crow[gn + j] = accv[i][jj * 4 + j] + (bias ? bias[gn + j] : 0.f);
            }
        }
    }
}

// ---------------- host launcher ----------------
extern "C" void kernel_launch(void* const* d_in, const int* in_sizes, int n_in,
                              void* d_out, int out_size) {
    (void)in_sizes; (void)n_in; (void)out_size;
    const float* x   = (const float*)d_in[0];
    const int*   ei  = (const int*)d_in[1];
    const float* W0  = (const float*)d_in[2];
    const float* as0 = (const float*)d_in[3];
    const float* ad0 = (const float*)d_in[4];
    const float* b0  = (const float*)d_in[5];
    const float* g0  = (const float*)d_in[6];
    const float* be0 = (const float*)d_in[7];
    const float* W1  = (const float*)d_in[8];
    const float* as1 = (const float*)d_in[9];
    const float* ad1 = (const float*)d_in[10];
    const float* b1  = (const float*)d_in[11];
    const float* g1  = (const float*)d_in[12];
    const float* be1 = (const float*)d_in[13];
    const float* Wc  = (const float*)d_in[14];
    const float* bc  = (const float*)d_in[15];
    float* out = (float*)d_out;
    const int* srcp = ei;
    const int* dstp = ei + EIN;

    void *p_counts, *p_cursor, *p_bnsum, *p_bnsum2;
    void *p_h0, *p_hin, *p_h1, *p_h2, *p_out0, *p_out1;
    cudaGetSymbolAddress(&p_counts, d_counts);
    cudaGetSymbolAddress(&p_cursor, d_cursor);
    cudaGetSymbolAddress(&p_bnsum,  d_bnsum);
    cudaGetSymbolAddress(&p_bnsum2, d_bnsum2);
    cudaGetSymbolAddress(&p_h0,   d_h0);
    cudaGetSymbolAddress(&p_hin,  d_hin);
    cudaGetSymbolAddress(&p_h1,   d_h1);
    cudaGetSymbolAddress(&p_h2,   d_h2);
    cudaGetSymbolAddress(&p_out0, d_out0);
    cudaGetSymbolAddress(&p_out1, d_out1);
    float* h0   = (float*)p_h0;
    float* hin  = (float*)p_hin;
    float* h1   = (float*)p_h1;
    float* h2   = (float*)p_h2;
    float* out0 = (float*)p_out0;
    float* out1 = (float*)p_out1;

    // ---- CSR build (shared by both layers) ----
    cudaMemsetAsync(p_counts, 0, (NN + 1) * sizeof(int));
    cudaMemsetAsync(p_cursor, 0, NN * sizeof(int));
    count_kernel<<<(ETOT + 255) / 256, 256>>>(dstp);
    scan_kernel<<<1, 1024>>>();
    place_kernel<<<(ETOT + 255) / 256, 256>>>(srcp, dstp);

    // ---- layer 0 ----
    gemm128<<<dim3(HID / 128, (NN + 127) / 128), 256>>>(x, W0, h0, nullptr, NN, HID, HID);
    attn_scores<<<(NN * NHEAD) / 8, 256>>>(h0, as0, ad0, HID / NHEAD);
    edge_softmax<<<(NN + 3) / 4, 128>>>();
    aggregate_c32<<<NN, HID>>>(h0, b0, out0);
    cudaMemsetAsync(p_bnsum, 0, HID * sizeof(float));
    cudaMemsetAsync(p_bnsum2, 0, HID * sizeof(float));
    bn_partial<<<128, HID>>>(out0);
    bn_final<<<1, HID>>>();
    bn_apply<<<(NN * HID + 255) / 256, 256>>>(out0, g0, be0, nullptr, hin);

    // ---- layer 1 ----
    gemm128<<<dim3((NHEAD * HID) / 128, (NN + 127) / 128), 256>>>(hin, W1, h1, nullptr, NN, NHEAD * HID, HID);
    attn_scores<<<(NN * NHEAD) / 8, 256>>>(h1, as1, ad1, HID);
    edge_softmax<<<(NN + 3) / 4, 128>>>();
    aggregate_c256_mean<<<NN, HID>>>(h1, b1, out1);
    cudaMemsetAsync(p_bnsum, 0, HID * sizeof(float));
    cudaMemsetAsync(p_bnsum2, 0, HID * sizeof(float));
    bn_partial<<<128, HID>>>(out1);
    bn_final<<<1, HID>>>();
    bn_apply<<<(NN * HID + 255) / 256, 256>>>(out1, g1, be1, hin, h2);

    // ---- classifier ----
    gemm128<<<dim3(1, (NN + 127) / 128), 256>>>(h2, Wc, out, bc, NN, 40, HID);
}